// round 5
// baseline (speedup 1.0000x reference)
#include <cuda_runtime.h>
#include <cstdint>

typedef unsigned long long u64;

#define NPTSALL    16384     // BATCH * N_PTS
#define NPTSHALF   8192
#define NFACES     10000
#define NPAIRS     5000      // NFACES / 2
#define NQTR       4
#define QTR_PAIRS  1250      // NPAIRS / NQTR
#define NSUB       50
#define SUB_PAIRS  25        // QTR_PAIRS / NSUB
#define SSCALE     10.0f

// Scratch (static __device__ arrays; no allocation)
__device__ float4 d_A[NPAIRS];             // (cx0, cx1, cy0, cy1) per center pair
__device__ float4 d_B[NPAIRS];             // (cz0, cz1, c2_0, c2_1) per center pair
__device__ float  d_qval[NQTR * NPTSALL];  // per-quarter min score per point
__device__ int    d_qsub[NQTR * NPTSALL];  // winning subtile base pair index

// ---------------- packed fp32x2 helpers ----------------
__device__ __forceinline__ u64 fma2(u64 a, u64 b, u64 c) {
    u64 d;
    asm("fma.rn.f32x2 %0, %1, %2, %3;" : "=l"(d) : "l"(a), "l"(b), "l"(c));
    return d;
}
__device__ __forceinline__ u64 pk2(float lo, float hi) {
    u64 v; asm("mov.b64 %0, {%1, %2};" : "=l"(v) : "f"(lo), "f"(hi)); return v;
}
__device__ __forceinline__ void upk2(u64 v, float& lo, float& hi) {
    asm("mov.b64 {%0, %1}, %2;" : "=f"(lo), "=f"(hi) : "l"(v));
}

// ---------------- 1) centers + |c|^2 (one thread per face) ----------------
__global__ void pack_centers_kernel(const float* __restrict__ V, const int* __restrict__ F) {
    int f = blockIdx.x * blockDim.x + threadIdx.x;
    if (f >= NFACES) return;
    int i0 = F[3*f+0], i1 = F[3*f+1], i2 = F[3*f+2];
    float x = (V[3*i0+0] + V[3*i1+0] + V[3*i2+0]) / 3.0f;
    float y = (V[3*i0+1] + V[3*i1+1] + V[3*i2+1]) / 3.0f;
    float z = (V[3*i0+2] + V[3*i1+2] + V[3*i2+2]) / 3.0f;
    float c2 = x*x + y*y + z*z;
    int p = f >> 1, h = f & 1;
    float* A = (float*)d_A;
    float* B = (float*)d_B;
    A[4*p + h]     = x;
    A[4*p + 2 + h] = y;
    B[4*p + h]     = z;
    B[4*p + 2 + h] = c2;
}

// ---------------- 2a) per-quarter min scan, 2 points per thread ----------------
// score_f = |c_f|^2 - 2 q . c_f  (|q|^2 dropped: argmin-invariant).
// grid = (NPTSALL/256, NQTR); 128 threads; thread handles points pt and pt+128.
// Tracks min VALUE per 25-pair subtile; strict < ascending => first-index ties.
__global__ void __launch_bounds__(128) knnA_kernel(const float* __restrict__ verts) {
    __shared__ ulonglong2 sA[QTR_PAIRS];   // 20 KB
    __shared__ ulonglong2 sB[QTR_PAIRS];   // 20 KB
    int tid = threadIdx.x;
    int qtr = blockIdx.y;
    int qbase = qtr * QTR_PAIRS;

    const ulonglong2* gA = (const ulonglong2*)d_A;
    const ulonglong2* gB = (const ulonglong2*)d_B;
    for (int i = tid; i < QTR_PAIRS; i += 128) { sA[i] = gA[qbase + i]; sB[i] = gB[qbase + i]; }
    __syncthreads();

    int ptA = blockIdx.x * 256 + tid;
    int ptB = ptA + 128;
    float qxA = verts[3*ptA+0], qyA = verts[3*ptA+1], qzA = verts[3*ptA+2];
    float qxB = verts[3*ptB+0], qyB = verts[3*ptB+1], qzB = verts[3*ptB+2];
    u64 qmxA = pk2(-2.0f*qxA, -2.0f*qxA);
    u64 qmyA = pk2(-2.0f*qyA, -2.0f*qyA);
    u64 qmzA = pk2(-2.0f*qzA, -2.0f*qzA);
    u64 qmxB = pk2(-2.0f*qxB, -2.0f*qxB);
    u64 qmyB = pk2(-2.0f*qyB, -2.0f*qyB);
    u64 qmzB = pk2(-2.0f*qzB, -2.0f*qzB);

    const float INF = __int_as_float(0x7f800000);
    float bestA = INF, bestB = INF;
    int subA = 0, subB = 0;

#pragma unroll 1
    for (int s = 0; s < NSUB; ++s) {
        int b = s * SUB_PAIRS;
        float a0 = INF, a1 = INF, b0 = INF, b1 = INF;
#pragma unroll 5
        for (int p = 0; p < SUB_PAIRS; ++p) {
            ulonglong2 A = sA[b + p];
            ulonglong2 B = sB[b + p];
            u64 zA = fma2(B.x, qmzA, B.y);
            u64 zB = fma2(B.x, qmzB, B.y);
            u64 scA = fma2(A.x, qmxA, fma2(A.y, qmyA, zA));
            u64 scB = fma2(A.x, qmxB, fma2(A.y, qmyB, zB));
            float lA, hA, lB, hB;
            upk2(scA, lA, hA); upk2(scB, lB, hB);
            a0 = fminf(a0, lA); a1 = fminf(a1, hA);
            b0 = fminf(b0, lB); b1 = fminf(b1, hB);
        }
        float smA = fminf(a0, a1);
        float smB = fminf(b0, b1);
        if (smA < bestA) { bestA = smA; subA = b; }   // strict <: earliest subtile wins
        if (smB < bestB) { bestB = smB; subB = b; }
    }
    d_qval[qtr * NPTSALL + ptA] = bestA;
    d_qsub[qtr * NPTSALL + ptA] = qbase + subA;
    d_qval[qtr * NPTSALL + ptB] = bestB;
    d_qsub[qtr * NPTSALL + ptB] = qbase + subB;
}

// ---------------- 2b + 3) combine/rescan + 4 x 50 Adam solve ----------------
// TWO independent points per thread (i, i+8192): interleaved Adam chains give
// 2-way ILP to cover the ~190-cycle serial dependency per iteration (each warp
// runs alone on its SMSP — no TLP available). Per-point arithmetic is the R2
// formulation VERBATIM; instruction interleaving across independent points
// cannot change either point's fp32 sequence.
__global__ void __launch_bounds__(64) solve_kernel(
    const float* __restrict__ verts,
    const float* __restrict__ MV,
    const float* __restrict__ MN,
    const int*   __restrict__ MF,
    float* __restrict__ out)
{
    int t0 = blockIdx.x * 64 + threadIdx.x;
    int idx[2] = { t0, t0 + NPTSHALF };

    float qx[2], qy[2], qz[2];
    int fid[2];

    const ulonglong2* gA = (const ulonglong2*)d_A;
    const ulonglong2* gB = (const ulonglong2*)d_B;

#pragma unroll
    for (int k = 0; k < 2; ++k) {
        int i = idx[k];
        qx[k] = verts[3*i+0]; qy[k] = verts[3*i+1]; qz[k] = verts[3*i+2];

        // ---- combine quarter mins (strict <, ascending => first-index ties) ----
        float best = d_qval[i]; int qi = 0;
#pragma unroll
        for (int q = 1; q < NQTR; ++q) {
            float v = d_qval[q * NPTSALL + i];
            if (v < best) { best = v; qi = q; }
        }
        int base = d_qsub[qi * NPTSALL + i];

        // ---- rescan winning 25-pair subtile, first bitwise-equal index ----
        u64 qmx = pk2(-2.0f*qx[k], -2.0f*qx[k]);
        u64 qmy = pk2(-2.0f*qy[k], -2.0f*qy[k]);
        u64 qmz = pk2(-2.0f*qz[k], -2.0f*qz[k]);
        int found = 0x7fffffff;
#pragma unroll 5
        for (int j = 0; j < SUB_PAIRS; ++j) {
            ulonglong2 a = gA[base + j];
            ulonglong2 b = gB[base + j];
            u64 sc = fma2(a.x, qmx, fma2(a.y, qmy, fma2(b.x, qmz, b.y)));
            float lo, hi; upk2(sc, lo, hi);
            if (lo == best) found = min(found, 2*(base + j));
            if (hi == best) found = min(found, 2*(base + j) + 1);
        }
        fid[k] = (found == 0x7fffffff) ? 0 : found;
    }

    // ---- geometry prologue (per point) ----
    float V0x[2], V0y[2], V0z[2], V1x[2], V1y[2], V1z[2], V2x[2], V2y[2], V2z[2];
    float N0x[2], N0y[2], N0z[2], N1x[2], N1y[2], N1z[2], N2x[2], N2y[2], N2z[2];
#pragma unroll
    for (int k = 0; k < 2; ++k) {
        int f = fid[k];
        int i0 = MF[3*f+0], i1 = MF[3*f+1], i2 = MF[3*f+2];
        V0x[k] = MV[3*i0+0]; V0y[k] = MV[3*i0+1]; V0z[k] = MV[3*i0+2];
        V1x[k] = MV[3*i1+0]; V1y[k] = MV[3*i1+1]; V1z[k] = MV[3*i1+2];
        V2x[k] = MV[3*i2+0]; V2y[k] = MV[3*i2+1]; V2z[k] = MV[3*i2+2];
        N0x[k] = MN[3*i0+0]; N0y[k] = MN[3*i0+1]; N0z[k] = MN[3*i0+2];
        N1x[k] = MN[3*i1+0]; N1y[k] = MN[3*i1+1]; N1z[k] = MN[3*i1+2];
        N2x[k] = MN[3*i2+0]; N2y[k] = MN[3*i2+1]; N2z[k] = MN[3*i2+2];
    }

    float tgx[2], tgy[2], tgz[2];
    float dVux[2], dVuy[2], dVuz[2], dVvx[2], dVvy[2], dVvz[2];
    float dNux[2], dNuy[2], dNuz[2], dNvx[2], dNvy[2], dNvz[2];
    float vwu[2], vwv[2];
#pragma unroll
    for (int k = 0; k < 2; ++k) {
        tgx[k] = SSCALE*qx[k]; tgy[k] = SSCALE*qy[k]; tgz[k] = SSCALE*qz[k];
        dVux[k] = V0x[k] - V2x[k]; dVuy[k] = V0y[k] - V2y[k]; dVuz[k] = V0z[k] - V2z[k];
        dVvx[k] = V1x[k] - V2x[k]; dVvy[k] = V1y[k] - V2y[k]; dVvz[k] = V1z[k] - V2z[k];
        dNux[k] = N0x[k] - N2x[k]; dNuy[k] = N0y[k] - N2y[k]; dNuz[k] = N0z[k] - N2z[k];
        dNvx[k] = N1x[k] - N2x[k]; dNvy[k] = N1y[k] - N2y[k]; dNvz[k] = N1z[k] - N2z[k];
        vwu[k] = 1.0f/3.0f; vwv[k] = 1.0f/3.0f;
    }

    const float B1 = 0.9f, B2 = 0.999f, LR = 0.01f, EPSA = 1e-8f;
    const float OB1 = 1.0f - 0.9f;
    const float OB2 = 1.0f - 0.999f;
    const float K   = (2.0f / 49152.0f) * SSCALE;  // 2/(3M) * S

#pragma unroll 1
    for (int outer = 0; outer < 4; ++outer) {
        float dd[2], du[2], dv[2];
        float mu[2], mv[2], md[2], vu[2], vv2[2], vd[2];
#pragma unroll
        for (int k = 0; k < 2; ++k) {
            float w0 = 1.0f - vwu[k] - vwv[k];
            float Px0 = fmaf(vwu[k], V0x[k], fmaf(vwv[k], V1x[k], w0 * V2x[k]));
            float Py0 = fmaf(vwu[k], V0y[k], fmaf(vwv[k], V1y[k], w0 * V2y[k]));
            float Pz0 = fmaf(vwu[k], V0z[k], fmaf(vwv[k], V1z[k], w0 * V2z[k]));
            float ex = Px0 - qx[k], ey = Py0 - qy[k], ez = Pz0 - qz[k];
            dd[k] = sqrtf(ex*ex + ey*ey + ez*ez);
            du[k] = 0.0f; dv[k] = 0.0f;
            mu[k] = 0.0f; mv[k] = 0.0f; md[k] = 0.0f;
            vu[k] = 0.0f; vv2[k] = 0.0f; vd[k] = 0.0f;
        }
        float b1t = 1.0f, b2t = 1.0f;

#pragma unroll 1
        for (int t = 0; t < 50; ++t) {
            b1t *= B1; b2t *= B2;
            float ic1 = __fdividef(1.0f, 1.0f - b1t);
            float ic2 = __fdividef(1.0f, 1.0f - b2t);
#pragma unroll
            for (int k = 0; k < 2; ++k) {
                float u = vwu[k] + du[k], v = vwv[k] + dv[k];
                float w = 1.0f - u - v;

                float Px = fmaf(u, V0x[k], fmaf(v, V1x[k], w * V2x[k]));
                float Py = fmaf(u, V0y[k], fmaf(v, V1y[k], w * V2y[k]));
                float Pz = fmaf(u, V0z[k], fmaf(v, V1z[k], w * V2z[k]));
                float Nx = fmaf(u, N0x[k], fmaf(v, N1x[k], w * N2x[k]));
                float Ny = fmaf(u, N0y[k], fmaf(v, N1y[k], w * N2y[k]));
                float Nz = fmaf(u, N0z[k], fmaf(v, N1z[k], w * N2z[k]));

                float nn = fmaf(Nx, Nx, fmaf(Ny, Ny, Nz * Nz));
                float l  = sqrtf(nn);
                float rl = __fdividef(1.0f, fmaxf(l, 1e-12f));
                float nx = Nx * rl, ny = Ny * rl, nz = Nz * rl;

                float sd = SSCALE * dd[k];
                float rx = fmaf(SSCALE, Px, fmaf(sd, nx, -tgx[k]));
                float ry = fmaf(SSCALE, Py, fmaf(sd, ny, -tgy[k]));
                float rz = fmaf(SSCALE, Pz, fmaf(sd, nz, -tgz[k]));

                float rn  = fmaf(rx, nx,      fmaf(ry, ny,      rz * nz));
                float rvu = fmaf(rx, dVux[k], fmaf(ry, dVuy[k], rz * dVuz[k]));
                float rvv = fmaf(rx, dVvx[k], fmaf(ry, dVvy[k], rz * dVvz[k]));
                float rnu = fmaf(rx, dNux[k], fmaf(ry, dNuy[k], rz * dNuz[k]));
                float rnv = fmaf(rx, dNvx[k], fmaf(ry, dNvy[k], rz * dNvz[k]));
                float ndu = fmaf(nx, dNux[k], fmaf(ny, dNuy[k], nz * dNuz[k]));
                float ndv = fmaf(nx, dNvx[k], fmaf(ny, dNvy[k], nz * dNvz[k]));

                float drl = dd[k] * rl;
                float gu = K * fmaf(drl, fmaf(-ndu, rn, rnu), rvu);
                float gv = K * fmaf(drl, fmaf(-ndv, rn, rnv), rvv);
                float gd = K * rn;

                mu[k] = fmaf(B1, mu[k], OB1 * gu);
                vu[k] = fmaf(B2, vu[k], OB2 * gu * gu);
                du[k] = fmaf(-LR, __fdividef(mu[k] * ic1, sqrtf(vu[k] * ic2) + EPSA), du[k]);

                mv[k] = fmaf(B1, mv[k], OB1 * gv);
                vv2[k] = fmaf(B2, vv2[k], OB2 * gv * gv);
                dv[k] = fmaf(-LR, __fdividef(mv[k] * ic1, sqrtf(vv2[k] * ic2) + EPSA), dv[k]);

                md[k] = fmaf(B1, md[k], OB1 * gd);
                vd[k] = fmaf(B2, vd[k], OB2 * gd * gd);
                dd[k] = fmaf(-LR, __fdividef(md[k] * ic1, sqrtf(vd[k] * ic2) + EPSA), dd[k]);
            }
        }
#pragma unroll
        for (int k = 0; k < 2; ++k) { vwu[k] += du[k]; vwv[k] += dv[k]; }
    }

    // Outputs, flattened tuple as float32: fidx | vw | outlier_mask
#pragma unroll
    for (int k = 0; k < 2; ++k) {
        int i = idx[k];
        out[i] = (float)fid[k];
        out[NPTSALL + 2*i + 0] = vwu[k];
        out[NPTSALL + 2*i + 1] = vwv[k];
        out[3*NPTSALL + i] = 0.0f;
    }
}

extern "C" void kernel_launch(void* const* d_in, const int* in_sizes, int n_in,
                              void* d_out, int out_size) {
    const float* verts  = (const float*)d_in[0];
    const float* mesh_V = (const float*)d_in[1];
    const float* mesh_N = (const float*)d_in[2];
    const int*   mesh_F = (const int*)d_in[3];
    float* out = (float*)d_out;

    pack_centers_kernel<<<(NFACES + 127) / 128, 128>>>(mesh_V, mesh_F);
    dim3 gridA(NPTSALL / 256, NQTR);
    knnA_kernel<<<gridA, 128>>>(verts);
    solve_kernel<<<NPTSHALF / 64, 64>>>(verts, mesh_V, mesh_N, mesh_F, out);
}

// round 7
// speedup vs baseline: 1.0690x; 1.0690x over previous
#include <cuda_runtime.h>
#include <cstdint>

typedef unsigned long long u64;

#define NPTSALL    16384     // BATCH * N_PTS
#define NPTSHALF   8192
#define NFACES     10000
#define NPAIRS     5000      // NFACES / 2
#define NQTR       4
#define QTR_PAIRS  1250      // NPAIRS / NQTR
#define NSUB       50
#define SUB_PAIRS  25        // QTR_PAIRS / NSUB
#define SSCALE     10.0f

// Scratch (static __device__ arrays; no allocation)
__device__ float4 d_A[NPAIRS];             // (cx0, cx1, cy0, cy1) per center pair
__device__ float4 d_B[NPAIRS];             // (cz0, cz1, c2_0, c2_1) per center pair
__device__ float  d_qval[NQTR * NPTSALL];  // per-quarter min score per point
__device__ int    d_qsub[NQTR * NPTSALL];  // winning subtile base pair index

// ---------------- packed fp32x2 helpers ----------------
__device__ __forceinline__ u64 fma2(u64 a, u64 b, u64 c) {
    u64 d;
    asm("fma.rn.f32x2 %0, %1, %2, %3;" : "=l"(d) : "l"(a), "l"(b), "l"(c));
    return d;
}
__device__ __forceinline__ u64 pk2(float lo, float hi) {
    u64 v; asm("mov.b64 %0, {%1, %2};" : "=l"(v) : "f"(lo), "f"(hi)); return v;
}
__device__ __forceinline__ void upk2(u64 v, float& lo, float& hi) {
    asm("mov.b64 {%0, %1}, %2;" : "=f"(lo), "=f"(hi) : "l"(v));
}

// ---------------- 1) centers + |c|^2 (one thread per face) ----------------
__global__ void pack_centers_kernel(const float* __restrict__ V, const int* __restrict__ F) {
    int f = blockIdx.x * blockDim.x + threadIdx.x;
    if (f >= NFACES) return;
    int i0 = F[3*f+0], i1 = F[3*f+1], i2 = F[3*f+2];
    float x = (V[3*i0+0] + V[3*i1+0] + V[3*i2+0]) / 3.0f;
    float y = (V[3*i0+1] + V[3*i1+1] + V[3*i2+1]) / 3.0f;
    float z = (V[3*i0+2] + V[3*i1+2] + V[3*i2+2]) / 3.0f;
    float c2 = x*x + y*y + z*z;
    int p = f >> 1, h = f & 1;
    float* A = (float*)d_A;
    float* B = (float*)d_B;
    A[4*p + h]     = x;
    A[4*p + 2 + h] = y;
    B[4*p + h]     = z;
    B[4*p + 2 + h] = c2;
}

// ---------------- 2a) per-quarter min scan, 2 points per thread ----------------
// score_f = |c_f|^2 - 2 q . c_f  (|q|^2 dropped: argmin-invariant).
// grid = (NPTSALL/256, NQTR); 128 threads; thread handles points pt and pt+128.
// Tracks min VALUE per 25-pair subtile; strict < ascending => first-index ties.
__global__ void __launch_bounds__(128) knnA_kernel(const float* __restrict__ verts) {
    __shared__ ulonglong2 sA[QTR_PAIRS];   // 20 KB
    __shared__ ulonglong2 sB[QTR_PAIRS];   // 20 KB
    int tid = threadIdx.x;
    int qtr = blockIdx.y;
    int qbase = qtr * QTR_PAIRS;

    const ulonglong2* gA = (const ulonglong2*)d_A;
    const ulonglong2* gB = (const ulonglong2*)d_B;
    for (int i = tid; i < QTR_PAIRS; i += 128) { sA[i] = gA[qbase + i]; sB[i] = gB[qbase + i]; }
    __syncthreads();

    int ptA = blockIdx.x * 256 + tid;
    int ptB = ptA + 128;
    float qxA = verts[3*ptA+0], qyA = verts[3*ptA+1], qzA = verts[3*ptA+2];
    float qxB = verts[3*ptB+0], qyB = verts[3*ptB+1], qzB = verts[3*ptB+2];
    u64 qmxA = pk2(-2.0f*qxA, -2.0f*qxA);
    u64 qmyA = pk2(-2.0f*qyA, -2.0f*qyA);
    u64 qmzA = pk2(-2.0f*qzA, -2.0f*qzA);
    u64 qmxB = pk2(-2.0f*qxB, -2.0f*qxB);
    u64 qmyB = pk2(-2.0f*qyB, -2.0f*qyB);
    u64 qmzB = pk2(-2.0f*qzB, -2.0f*qzB);

    const float INF = __int_as_float(0x7f800000);
    float bestA = INF, bestB = INF;
    int subA = 0, subB = 0;

#pragma unroll 1
    for (int s = 0; s < NSUB; ++s) {
        int b = s * SUB_PAIRS;
        float a0 = INF, a1 = INF, b0 = INF, b1 = INF;
#pragma unroll 5
        for (int p = 0; p < SUB_PAIRS; ++p) {
            ulonglong2 A = sA[b + p];
            ulonglong2 B = sB[b + p];
            u64 zA = fma2(B.x, qmzA, B.y);
            u64 zB = fma2(B.x, qmzB, B.y);
            u64 scA = fma2(A.x, qmxA, fma2(A.y, qmyA, zA));
            u64 scB = fma2(A.x, qmxB, fma2(A.y, qmyB, zB));
            float lA, hA, lB, hB;
            upk2(scA, lA, hA); upk2(scB, lB, hB);
            a0 = fminf(a0, lA); a1 = fminf(a1, hA);
            b0 = fminf(b0, lB); b1 = fminf(b1, hB);
        }
        float smA = fminf(a0, a1);
        float smB = fminf(b0, b1);
        if (smA < bestA) { bestA = smA; subA = b; }   // strict <: earliest subtile wins
        if (smB < bestB) { bestB = smB; subB = b; }
    }
    d_qval[qtr * NPTSALL + ptA] = bestA;
    d_qsub[qtr * NPTSALL + ptA] = qbase + subA;
    d_qval[qtr * NPTSALL + ptB] = bestB;
    d_qsub[qtr * NPTSALL + ptB] = qbase + subB;
}

// ---------------- helper: combine + rescan for one point ----------------
__device__ __forceinline__ int find_fid(int i, float qx, float qy, float qz) {
    float best = d_qval[i]; int qi = 0;
#pragma unroll
    for (int q = 1; q < NQTR; ++q) {
        float v = d_qval[q * NPTSALL + i];
        if (v < best) { best = v; qi = q; }
    }
    int base = d_qsub[qi * NPTSALL + i];

    u64 qmx = pk2(-2.0f*qx, -2.0f*qx);
    u64 qmy = pk2(-2.0f*qy, -2.0f*qy);
    u64 qmz = pk2(-2.0f*qz, -2.0f*qz);
    const ulonglong2* gA = (const ulonglong2*)d_A;
    const ulonglong2* gB = (const ulonglong2*)d_B;
    int found = 0x7fffffff;
#pragma unroll 5
    for (int j = 0; j < SUB_PAIRS; ++j) {
        ulonglong2 a = gA[base + j];
        ulonglong2 b = gB[base + j];
        u64 sc = fma2(a.x, qmx, fma2(a.y, qmy, fma2(b.x, qmz, b.y)));
        float lo, hi; upk2(sc, lo, hi);
        if (lo == best) found = min(found, 2*(base + j));
        if (hi == best) found = min(found, 2*(base + j) + 1);
    }
    return (found == 0x7fffffff) ? 0 : found;
}

// ---------------- 2b + 3) combine/rescan + 4 x 50 Adam solve, ILP2 scalar ----------------
// Two independent points per thread (i, i+8192), state in PURE SCALARS,
// __launch_bounds__(64,1) => no reg cap, no spill. Per-point fp32 op sequence
// is the R2/R4 formulation VERBATIM, including the RUNTIME inline ic1/ic2
// computation (no precomputed table: compile-time constant folding of
// __fdividef produces different bits than the runtime MUFU path — R6 lesson).
__global__ void __launch_bounds__(64, 1) solve_kernel(
    const float* __restrict__ verts,
    const float* __restrict__ MV,
    const float* __restrict__ MN,
    const int*   __restrict__ MF,
    float* __restrict__ out)
{
    int ia = blockIdx.x * 64 + threadIdx.x;
    int ib = ia + NPTSHALF;

    float qxa = verts[3*ia+0], qya = verts[3*ia+1], qza = verts[3*ia+2];
    float qxb = verts[3*ib+0], qyb = verts[3*ib+1], qzb = verts[3*ib+2];

    int fida = find_fid(ia, qxa, qya, qza);
    int fidb = find_fid(ib, qxb, qyb, qzb);

    int a0 = MF[3*fida+0], a1 = MF[3*fida+1], a2 = MF[3*fida+2];
    int b0 = MF[3*fidb+0], b1 = MF[3*fidb+1], b2 = MF[3*fidb+2];

    float V0xa = MV[3*a0+0], V0ya = MV[3*a0+1], V0za = MV[3*a0+2];
    float V1xa = MV[3*a1+0], V1ya = MV[3*a1+1], V1za = MV[3*a1+2];
    float V2xa = MV[3*a2+0], V2ya = MV[3*a2+1], V2za = MV[3*a2+2];
    float N0xa = MN[3*a0+0], N0ya = MN[3*a0+1], N0za = MN[3*a0+2];
    float N1xa = MN[3*a1+0], N1ya = MN[3*a1+1], N1za = MN[3*a1+2];
    float N2xa = MN[3*a2+0], N2ya = MN[3*a2+1], N2za = MN[3*a2+2];

    float V0xb = MV[3*b0+0], V0yb = MV[3*b0+1], V0zb = MV[3*b0+2];
    float V1xb = MV[3*b1+0], V1yb = MV[3*b1+1], V1zb = MV[3*b1+2];
    float V2xb = MV[3*b2+0], V2yb = MV[3*b2+1], V2zb = MV[3*b2+2];
    float N0xb = MN[3*b0+0], N0yb = MN[3*b0+1], N0zb = MN[3*b0+2];
    float N1xb = MN[3*b1+0], N1yb = MN[3*b1+1], N1zb = MN[3*b1+2];
    float N2xb = MN[3*b2+0], N2yb = MN[3*b2+1], N2zb = MN[3*b2+2];

    float tgxa = SSCALE*qxa, tgya = SSCALE*qya, tgza = SSCALE*qza;
    float tgxb = SSCALE*qxb, tgyb = SSCALE*qyb, tgzb = SSCALE*qzb;

    float dVuxa = V0xa - V2xa, dVuya = V0ya - V2ya, dVuza = V0za - V2za;
    float dVvxa = V1xa - V2xa, dVvya = V1ya - V2ya, dVvza = V1za - V2za;
    float dNuxa = N0xa - N2xa, dNuya = N0ya - N2ya, dNuza = N0za - N2za;
    float dNvxa = N1xa - N2xa, dNvya = N1ya - N2ya, dNvza = N1za - N2za;

    float dVuxb = V0xb - V2xb, dVuyb = V0yb - V2yb, dVuzb = V0zb - V2zb;
    float dVvxb = V1xb - V2xb, dVvyb = V1yb - V2yb, dVvzb = V1zb - V2zb;
    float dNuxb = N0xb - N2xb, dNuyb = N0yb - N2yb, dNuzb = N0zb - N2zb;
    float dNvxb = N1xb - N2xb, dNvyb = N1yb - N2yb, dNvzb = N1zb - N2zb;

    const float B1 = 0.9f, B2 = 0.999f, LR = 0.01f, EPSA = 1e-8f;
    const float OB1 = 1.0f - 0.9f;
    const float OB2 = 1.0f - 0.999f;
    const float K   = (2.0f / 49152.0f) * SSCALE;  // 2/(3M) * S

    float vwua = 1.0f/3.0f, vwva = 1.0f/3.0f;
    float vwub = 1.0f/3.0f, vwvb = 1.0f/3.0f;

#pragma unroll 1
    for (int outer = 0; outer < 4; ++outer) {
        float w0a = 1.0f - vwua - vwva;
        float Px0a = fmaf(vwua, V0xa, fmaf(vwva, V1xa, w0a * V2xa));
        float Py0a = fmaf(vwua, V0ya, fmaf(vwva, V1ya, w0a * V2ya));
        float Pz0a = fmaf(vwua, V0za, fmaf(vwva, V1za, w0a * V2za));
        float exa = Px0a - qxa, eya = Py0a - qya, eza = Pz0a - qza;
        float dda = sqrtf(exa*exa + eya*eya + eza*eza);

        float w0b = 1.0f - vwub - vwvb;
        float Px0b = fmaf(vwub, V0xb, fmaf(vwvb, V1xb, w0b * V2xb));
        float Py0b = fmaf(vwub, V0yb, fmaf(vwvb, V1yb, w0b * V2yb));
        float Pz0b = fmaf(vwub, V0zb, fmaf(vwvb, V1zb, w0b * V2zb));
        float exb = Px0b - qxb, eyb = Py0b - qyb, ezb = Pz0b - qzb;
        float ddb = sqrtf(exb*exb + eyb*eyb + ezb*ezb);

        float dua = 0.0f, dva = 0.0f, mua = 0.0f, mva = 0.0f, mda = 0.0f;
        float vua = 0.0f, vva = 0.0f, vda = 0.0f;
        float dub = 0.0f, dvb = 0.0f, mub = 0.0f, mvb = 0.0f, mdb = 0.0f;
        float vub = 0.0f, vvb = 0.0f, vdb = 0.0f;
        float b1t = 1.0f, b2t = 1.0f;

#pragma unroll 1
        for (int t = 0; t < 50; ++t) {
            b1t *= B1; b2t *= B2;
            float ic1 = __fdividef(1.0f, 1.0f - b1t);
            float ic2 = __fdividef(1.0f, 1.0f - b2t);

            float ua = vwua + dua, va = vwva + dva;
            float ub = vwub + dub, vb = vwvb + dvb;
            float wa = 1.0f - ua - va;
            float wb = 1.0f - ub - vb;

            float Pxa = fmaf(ua, V0xa, fmaf(va, V1xa, wa * V2xa));
            float Pxb = fmaf(ub, V0xb, fmaf(vb, V1xb, wb * V2xb));
            float Pya = fmaf(ua, V0ya, fmaf(va, V1ya, wa * V2ya));
            float Pyb = fmaf(ub, V0yb, fmaf(vb, V1yb, wb * V2yb));
            float Pza = fmaf(ua, V0za, fmaf(va, V1za, wa * V2za));
            float Pzb = fmaf(ub, V0zb, fmaf(vb, V1zb, wb * V2zb));
            float Nxa = fmaf(ua, N0xa, fmaf(va, N1xa, wa * N2xa));
            float Nxb = fmaf(ub, N0xb, fmaf(vb, N1xb, wb * N2xb));
            float Nya = fmaf(ua, N0ya, fmaf(va, N1ya, wa * N2ya));
            float Nyb = fmaf(ub, N0yb, fmaf(vb, N1yb, wb * N2yb));
            float Nza = fmaf(ua, N0za, fmaf(va, N1za, wa * N2za));
            float Nzb = fmaf(ub, N0zb, fmaf(vb, N1zb, wb * N2zb));

            float nna = fmaf(Nxa, Nxa, fmaf(Nya, Nya, Nza * Nza));
            float nnb = fmaf(Nxb, Nxb, fmaf(Nyb, Nyb, Nzb * Nzb));
            float la  = sqrtf(nna);
            float lb  = sqrtf(nnb);
            float rla = __fdividef(1.0f, fmaxf(la, 1e-12f));
            float rlb = __fdividef(1.0f, fmaxf(lb, 1e-12f));
            float nxa = Nxa * rla, nya = Nya * rla, nza = Nza * rla;
            float nxb = Nxb * rlb, nyb = Nyb * rlb, nzb = Nzb * rlb;

            float sda = SSCALE * dda;
            float sdb = SSCALE * ddb;
            float rxa = fmaf(SSCALE, Pxa, fmaf(sda, nxa, -tgxa));
            float rxb = fmaf(SSCALE, Pxb, fmaf(sdb, nxb, -tgxb));
            float rya = fmaf(SSCALE, Pya, fmaf(sda, nya, -tgya));
            float ryb = fmaf(SSCALE, Pyb, fmaf(sdb, nyb, -tgyb));
            float rza = fmaf(SSCALE, Pza, fmaf(sda, nza, -tgza));
            float rzb = fmaf(SSCALE, Pzb, fmaf(sdb, nzb, -tgzb));

            float rna  = fmaf(rxa, nxa,   fmaf(rya, nya,   rza * nza));
            float rnb  = fmaf(rxb, nxb,   fmaf(ryb, nyb,   rzb * nzb));
            float rvua = fmaf(rxa, dVuxa, fmaf(rya, dVuya, rza * dVuza));
            float rvub = fmaf(rxb, dVuxb, fmaf(ryb, dVuyb, rzb * dVuzb));
            float rvva = fmaf(rxa, dVvxa, fmaf(rya, dVvya, rza * dVvza));
            float rvvb = fmaf(rxb, dVvxb, fmaf(ryb, dVvyb, rzb * dVvzb));
            float rnua = fmaf(rxa, dNuxa, fmaf(rya, dNuya, rza * dNuza));
            float rnub = fmaf(rxb, dNuxb, fmaf(ryb, dNuyb, rzb * dNuzb));
            float rnva = fmaf(rxa, dNvxa, fmaf(rya, dNvya, rza * dNvza));
            float rnvb = fmaf(rxb, dNvxb, fmaf(ryb, dNvyb, rzb * dNvzb));
            float ndua = fmaf(nxa, dNuxa, fmaf(nya, dNuya, nza * dNuza));
            float ndub = fmaf(nxb, dNuxb, fmaf(nyb, dNuyb, nzb * dNuzb));
            float ndva = fmaf(nxa, dNvxa, fmaf(nya, dNvya, nza * dNvza));
            float ndvb = fmaf(nxb, dNvxb, fmaf(nyb, dNvyb, nzb * dNvzb));

            float drla = dda * rla;
            float drlb = ddb * rlb;
            float gua = K * fmaf(drla, fmaf(-ndua, rna, rnua), rvua);
            float gub = K * fmaf(drlb, fmaf(-ndub, rnb, rnub), rvub);
            float gva = K * fmaf(drla, fmaf(-ndva, rna, rnva), rvva);
            float gvb = K * fmaf(drlb, fmaf(-ndvb, rnb, rnvb), rvvb);
            float gda = K * rna;
            float gdb = K * rnb;

            mua = fmaf(B1, mua, OB1 * gua);
            mub = fmaf(B1, mub, OB1 * gub);
            vua = fmaf(B2, vua, OB2 * gua * gua);
            vub = fmaf(B2, vub, OB2 * gub * gub);
            dua = fmaf(-LR, __fdividef(mua * ic1, sqrtf(vua * ic2) + EPSA), dua);
            dub = fmaf(-LR, __fdividef(mub * ic1, sqrtf(vub * ic2) + EPSA), dub);

            mva = fmaf(B1, mva, OB1 * gva);
            mvb = fmaf(B1, mvb, OB1 * gvb);
            vva = fmaf(B2, vva, OB2 * gva * gva);
            vvb = fmaf(B2, vvb, OB2 * gvb * gvb);
            dva = fmaf(-LR, __fdividef(mva * ic1, sqrtf(vva * ic2) + EPSA), dva);
            dvb = fmaf(-LR, __fdividef(mvb * ic1, sqrtf(vvb * ic2) + EPSA), dvb);

            mda = fmaf(B1, mda, OB1 * gda);
            mdb = fmaf(B1, mdb, OB1 * gdb);
            vda = fmaf(B2, vda, OB2 * gda * gda);
            vdb = fmaf(B2, vdb, OB2 * gdb * gdb);
            dda = fmaf(-LR, __fdividef(mda * ic1, sqrtf(vda * ic2) + EPSA), dda);
            ddb = fmaf(-LR, __fdividef(mdb * ic1, sqrtf(vdb * ic2) + EPSA), ddb);
        }
        vwua += dua; vwva += dva;
        vwub += dub; vwvb += dvb;
    }

    // Outputs, flattened tuple as float32: fidx | vw | outlier_mask
    out[ia] = (float)fida;
    out[NPTSALL + 2*ia + 0] = vwua;
    out[NPTSALL + 2*ia + 1] = vwva;
    out[3*NPTSALL + ia] = 0.0f;
    out[ib] = (float)fidb;
    out[NPTSALL + 2*ib + 0] = vwub;
    out[NPTSALL + 2*ib + 1] = vwvb;
    out[3*NPTSALL + ib] = 0.0f;
}

extern "C" void kernel_launch(void* const* d_in, const int* in_sizes, int n_in,
                              void* d_out, int out_size) {
    const float* verts  = (const float*)d_in[0];
    const float* mesh_V = (const float*)d_in[1];
    const float* mesh_N = (const float*)d_in[2];
    const int*   mesh_F = (const int*)d_in[3];
    float* out = (float*)d_out;

    pack_centers_kernel<<<(NFACES + 127) / 128, 128>>>(mesh_V, mesh_F);
    dim3 gridA(NPTSALL / 256, NQTR);
    knnA_kernel<<<gridA, 128>>>(verts);
    solve_kernel<<<NPTSHALF / 64, 64>>>(verts, mesh_V, mesh_N, mesh_F, out);
}

// round 8
// speedup vs baseline: 1.5793x; 1.4773x over previous
#include <cuda_runtime.h>
#include <cstdint>

typedef unsigned long long u64;

#define NPTSALL    16384     // BATCH * N_PTS
#define NFACES     10000
#define NPAIRS     5000      // NFACES / 2
#define NOCT       8
#define OCT_PAIRS  625       // NPAIRS / NOCT
#define NSUB       25
#define SUB_PAIRS  25        // OCT_PAIRS / NSUB
#define SSCALE     10.0f

// Scratch (static __device__ arrays; no allocation)
__device__ float4 d_A[NPAIRS];             // (cx0, cx1, cy0, cy1) per center pair
__device__ float4 d_B[NPAIRS];             // (cz0, cz1, c2_0, c2_1) per center pair
__device__ float  d_qval[NOCT * NPTSALL];  // per-octant min score per point
__device__ int    d_qsub[NOCT * NPTSALL];  // winning subtile base pair index

// ---------------- packed fp32x2 helpers ----------------
__device__ __forceinline__ u64 fma2(u64 a, u64 b, u64 c) {
    u64 d;
    asm("fma.rn.f32x2 %0, %1, %2, %3;" : "=l"(d) : "l"(a), "l"(b), "l"(c));
    return d;
}
__device__ __forceinline__ u64 pk2(float lo, float hi) {
    u64 v; asm("mov.b64 %0, {%1, %2};" : "=l"(v) : "f"(lo), "f"(hi)); return v;
}
__device__ __forceinline__ void upk2(u64 v, float& lo, float& hi) {
    asm("mov.b64 {%0, %1}, %2;" : "=f"(lo), "=f"(hi) : "l"(v));
}

// ---------------- 1) centers + |c|^2 (one thread per face) ----------------
__global__ void pack_centers_kernel(const float* __restrict__ V, const int* __restrict__ F) {
    int f = blockIdx.x * blockDim.x + threadIdx.x;
    if (f >= NFACES) return;
    int i0 = F[3*f+0], i1 = F[3*f+1], i2 = F[3*f+2];
    float x = (V[3*i0+0] + V[3*i1+0] + V[3*i2+0]) / 3.0f;
    float y = (V[3*i0+1] + V[3*i1+1] + V[3*i2+1]) / 3.0f;
    float z = (V[3*i0+2] + V[3*i1+2] + V[3*i2+2]) / 3.0f;
    float c2 = x*x + y*y + z*z;
    int p = f >> 1, h = f & 1;
    float* A = (float*)d_A;
    float* B = (float*)d_B;
    A[4*p + h]     = x;
    A[4*p + 2 + h] = y;
    B[4*p + h]     = z;
    B[4*p + 2 + h] = c2;
}

// ---------------- 2a) per-octant min scan, 2 points per thread ----------------
// score_f = |c_f|^2 - 2 q . c_f  (|q|^2 dropped: argmin-invariant).
// grid = (NPTSALL/256, NOCT) = (64, 8) = 512 blocks -> 3.46 blocks/SM, so every
// SMSP carries >=3 warps and issues at ~1 inst/cyc (not the lone-warp rt-2 floor).
// Tracks min VALUE per 25-pair subtile; strict < ascending => first-index ties.
__global__ void __launch_bounds__(128) knnA_kernel(const float* __restrict__ verts) {
    __shared__ ulonglong2 sA[OCT_PAIRS];   // 10 KB
    __shared__ ulonglong2 sB[OCT_PAIRS];   // 10 KB
    int tid = threadIdx.x;
    int oct = blockIdx.y;
    int obase = oct * OCT_PAIRS;

    const ulonglong2* gA = (const ulonglong2*)d_A;
    const ulonglong2* gB = (const ulonglong2*)d_B;
    for (int i = tid; i < OCT_PAIRS; i += 128) { sA[i] = gA[obase + i]; sB[i] = gB[obase + i]; }
    __syncthreads();

    int ptA = blockIdx.x * 256 + tid;
    int ptB = ptA + 128;
    float qxA = verts[3*ptA+0], qyA = verts[3*ptA+1], qzA = verts[3*ptA+2];
    float qxB = verts[3*ptB+0], qyB = verts[3*ptB+1], qzB = verts[3*ptB+2];
    u64 qmxA = pk2(-2.0f*qxA, -2.0f*qxA);
    u64 qmyA = pk2(-2.0f*qyA, -2.0f*qyA);
    u64 qmzA = pk2(-2.0f*qzA, -2.0f*qzA);
    u64 qmxB = pk2(-2.0f*qxB, -2.0f*qxB);
    u64 qmyB = pk2(-2.0f*qyB, -2.0f*qyB);
    u64 qmzB = pk2(-2.0f*qzB, -2.0f*qzB);

    const float INF = __int_as_float(0x7f800000);
    float bestA = INF, bestB = INF;
    int subA = 0, subB = 0;

#pragma unroll 1
    for (int s = 0; s < NSUB; ++s) {
        int b = s * SUB_PAIRS;
        float a0 = INF, a1 = INF, b0 = INF, b1 = INF;
#pragma unroll 5
        for (int p = 0; p < SUB_PAIRS; ++p) {
            ulonglong2 A = sA[b + p];
            ulonglong2 B = sB[b + p];
            u64 zA = fma2(B.x, qmzA, B.y);
            u64 zB = fma2(B.x, qmzB, B.y);
            u64 scA = fma2(A.x, qmxA, fma2(A.y, qmyA, zA));
            u64 scB = fma2(A.x, qmxB, fma2(A.y, qmyB, zB));
            float lA, hA, lB, hB;
            upk2(scA, lA, hA); upk2(scB, lB, hB);
            a0 = fminf(a0, lA); a1 = fminf(a1, hA);
            b0 = fminf(b0, lB); b1 = fminf(b1, hB);
        }
        float smA = fminf(a0, a1);
        float smB = fminf(b0, b1);
        if (smA < bestA) { bestA = smA; subA = b; }   // strict <: earliest subtile wins
        if (smB < bestB) { bestB = smB; subB = b; }
    }
    d_qval[oct * NPTSALL + ptA] = bestA;
    d_qsub[oct * NPTSALL + ptA] = obase + subA;
    d_qval[oct * NPTSALL + ptB] = bestB;
    d_qsub[oct * NPTSALL + ptB] = obase + subB;
}

// ---------------- 2b + 3) combine/rescan + 4 x 50 Adam solve ----------------
// R4-form: ONE point per thread, 128-thread blocks. At <=1 warp/SMSP the rt-2
// issue floor binds, so per-iter time ~ 2 * inst_count; Adam numerics are the
// validated R2/R4 formulation VERBATIM.
__global__ void __launch_bounds__(128) solve_kernel(
    const float* __restrict__ verts,
    const float* __restrict__ MV,
    const float* __restrict__ MN,
    const int*   __restrict__ MF,
    float* __restrict__ out)
{
    int i = blockIdx.x * 128 + threadIdx.x;

    float qx = verts[3*i+0], qy = verts[3*i+1], qz = verts[3*i+2];

    // ---- combine octant mins (strict <, ascending => first-index ties) ----
    float best = d_qval[i]; int qi = 0;
#pragma unroll
    for (int q = 1; q < NOCT; ++q) {
        float v = d_qval[q * NPTSALL + i];
        if (v < best) { best = v; qi = q; }
    }
    int base = d_qsub[qi * NPTSALL + i];

    // ---- rescan winning 25-pair subtile, first bitwise-equal index ----
    u64 qmx = pk2(-2.0f*qx, -2.0f*qx);
    u64 qmy = pk2(-2.0f*qy, -2.0f*qy);
    u64 qmz = pk2(-2.0f*qz, -2.0f*qz);
    const ulonglong2* gA = (const ulonglong2*)d_A;
    const ulonglong2* gB = (const ulonglong2*)d_B;
    int found = 0x7fffffff;
#pragma unroll 5
    for (int j = 0; j < SUB_PAIRS; ++j) {
        ulonglong2 a = gA[base + j];
        ulonglong2 b = gB[base + j];
        u64 sc = fma2(a.x, qmx, fma2(a.y, qmy, fma2(b.x, qmz, b.y)));
        float lo, hi; upk2(sc, lo, hi);
        if (lo == best) found = min(found, 2*(base + j));
        if (hi == best) found = min(found, 2*(base + j) + 1);
    }
    int fid = (found == 0x7fffffff) ? 0 : found;   // guaranteed found; OOB guard

    // ---- Adam solve (numerics identical to R2/R4) ----
    int i0 = MF[3*fid+0], i1 = MF[3*fid+1], i2 = MF[3*fid+2];

    float V0x = MV[3*i0+0], V0y = MV[3*i0+1], V0z = MV[3*i0+2];
    float V1x = MV[3*i1+0], V1y = MV[3*i1+1], V1z = MV[3*i1+2];
    float V2x = MV[3*i2+0], V2y = MV[3*i2+1], V2z = MV[3*i2+2];
    float N0x = MN[3*i0+0], N0y = MN[3*i0+1], N0z = MN[3*i0+2];
    float N1x = MN[3*i1+0], N1y = MN[3*i1+1], N1z = MN[3*i1+2];
    float N2x = MN[3*i2+0], N2y = MN[3*i2+1], N2z = MN[3*i2+2];

    float tgx = SSCALE*qx, tgy = SSCALE*qy, tgz = SSCALE*qz;

    float dVux = V0x - V2x, dVuy = V0y - V2y, dVuz = V0z - V2z;
    float dVvx = V1x - V2x, dVvy = V1y - V2y, dVvz = V1z - V2z;
    float dNux = N0x - N2x, dNuy = N0y - N2y, dNuz = N0z - N2z;
    float dNvx = N1x - N2x, dNvy = N1y - N2y, dNvz = N1z - N2z;

    const float B1 = 0.9f, B2 = 0.999f, LR = 0.01f, EPSA = 1e-8f;
    const float OB1 = 1.0f - 0.9f;
    const float OB2 = 1.0f - 0.999f;
    const float K   = (2.0f / 49152.0f) * SSCALE;  // 2/(3M) * S

    float vwu = 1.0f/3.0f, vwv = 1.0f/3.0f;

#pragma unroll 1
    for (int outer = 0; outer < 4; ++outer) {
        float w0 = 1.0f - vwu - vwv;
        float Px0 = fmaf(vwu, V0x, fmaf(vwv, V1x, w0 * V2x));
        float Py0 = fmaf(vwu, V0y, fmaf(vwv, V1y, w0 * V2y));
        float Pz0 = fmaf(vwu, V0z, fmaf(vwv, V1z, w0 * V2z));
        float ex = Px0 - qx, ey = Py0 - qy, ez = Pz0 - qz;
        float dd = sqrtf(ex*ex + ey*ey + ez*ez);

        float du = 0.0f, dv = 0.0f;
        float mu = 0.0f, mv = 0.0f, md = 0.0f;
        float vu = 0.0f, vvv = 0.0f, vd = 0.0f;
        float b1t = 1.0f, b2t = 1.0f;

#pragma unroll 1
        for (int t = 0; t < 50; ++t) {
            b1t *= B1; b2t *= B2;
            float u = vwu + du, v = vwv + dv;
            float w = 1.0f - u - v;

            float Px = fmaf(u, V0x, fmaf(v, V1x, w * V2x));
            float Py = fmaf(u, V0y, fmaf(v, V1y, w * V2y));
            float Pz = fmaf(u, V0z, fmaf(v, V1z, w * V2z));
            float Nx = fmaf(u, N0x, fmaf(v, N1x, w * N2x));
            float Ny = fmaf(u, N0y, fmaf(v, N1y, w * N2y));
            float Nz = fmaf(u, N0z, fmaf(v, N1z, w * N2z));

            float nn = fmaf(Nx, Nx, fmaf(Ny, Ny, Nz * Nz));
            float l  = sqrtf(nn);
            float rl = __fdividef(1.0f, fmaxf(l, 1e-12f));
            float nx = Nx * rl, ny = Ny * rl, nz = Nz * rl;

            float sd = SSCALE * dd;
            float rx = fmaf(SSCALE, Px, fmaf(sd, nx, -tgx));
            float ry = fmaf(SSCALE, Py, fmaf(sd, ny, -tgy));
            float rz = fmaf(SSCALE, Pz, fmaf(sd, nz, -tgz));

            float rn  = fmaf(rx, nx,   fmaf(ry, ny,   rz * nz));
            float rvu = fmaf(rx, dVux, fmaf(ry, dVuy, rz * dVuz));
            float rvv = fmaf(rx, dVvx, fmaf(ry, dVvy, rz * dVvz));
            float rnu = fmaf(rx, dNux, fmaf(ry, dNuy, rz * dNuz));
            float rnv = fmaf(rx, dNvx, fmaf(ry, dNvy, rz * dNvz));
            float ndu = fmaf(nx, dNux, fmaf(ny, dNuy, nz * dNuz));
            float ndv = fmaf(nx, dNvx, fmaf(ny, dNvy, nz * dNvz));

            float drl = dd * rl;
            float gu = K * fmaf(drl, fmaf(-ndu, rn, rnu), rvu);
            float gv = K * fmaf(drl, fmaf(-ndv, rn, rnv), rvv);
            float gd = K * rn;

            float ic1 = __fdividef(1.0f, 1.0f - b1t);
            float ic2 = __fdividef(1.0f, 1.0f - b2t);

            mu = fmaf(B1, mu, OB1 * gu);
            vu = fmaf(B2, vu, OB2 * gu * gu);
            du = fmaf(-LR, __fdividef(mu * ic1, sqrtf(vu * ic2) + EPSA), du);

            mv = fmaf(B1, mv, OB1 * gv);
            vvv = fmaf(B2, vvv, OB2 * gv * gv);
            dv = fmaf(-LR, __fdividef(mv * ic1, sqrtf(vvv * ic2) + EPSA), dv);

            md = fmaf(B1, md, OB1 * gd);
            vd = fmaf(B2, vd, OB2 * gd * gd);
            dd = fmaf(-LR, __fdividef(md * ic1, sqrtf(vd * ic2) + EPSA), dd);
        }
        vwu += du; vwv += dv;
    }

    // Outputs, flattened tuple as float32: fidx | vw | outlier_mask
    out[i] = (float)fid;
    out[NPTSALL + 2*i + 0] = vwu;
    out[NPTSALL + 2*i + 1] = vwv;
    out[3*NPTSALL + i] = 0.0f;
}

extern "C" void kernel_launch(void* const* d_in, const int* in_sizes, int n_in,
                              void* d_out, int out_size) {
    const float* verts  = (const float*)d_in[0];
    const float* mesh_V = (const float*)d_in[1];
    const float* mesh_N = (const float*)d_in[2];
    const int*   mesh_F = (const int*)d_in[3];
    float* out = (float*)d_out;

    pack_centers_kernel<<<(NFACES + 127) / 128, 128>>>(mesh_V, mesh_F);
    dim3 gridA(NPTSALL / 256, NOCT);
    knnA_kernel<<<gridA, 128>>>(verts);
    solve_kernel<<<NPTSALL / 128, 128>>>(verts, mesh_V, mesh_N, mesh_F, out);
}